// round 3
// baseline (speedup 1.0000x reference)
#include <cuda_runtime.h>
#include <math.h>

#define BB 2
#define TT 2048
#define DD 1024
#define HH 16
#define DK 64

// Scratch (allocation-free rule: __device__ globals)
__device__ float g_Q[BB*TT*DD];
__device__ float g_K[BB*TT*DD];
__device__ float g_V[BB*TT*DD];
__device__ float g_C[BB*TT*DD];

// ---------------------------------------------------------------------------
// SGEMM: Y[n, m] = sum_k X[n,k] * W[m,k] + bias[m]
// X: [4096, 1024] row-major, W: [1024, 1024] row-major (used transposed)
// BM=BN=64, BK=16, 256 threads, 4x4 register tile per thread.
// ---------------------------------------------------------------------------
__global__ __launch_bounds__(256) void gemm_bias_kernel(
    const float* __restrict__ X, const float* __restrict__ W,
    const float* __restrict__ bias, float* __restrict__ Y)
{
    __shared__ float Xs[16][68];   // [k][row], padded
    __shared__ float Ws[16][68];   // [k][col], padded

    const int tid = threadIdx.x;
    const int tx = tid & 15;        // 0..15 -> output cols
    const int ty = tid >> 4;        // 0..15 -> output rows
    const int rowBase = blockIdx.y * 64;
    const int colBase = blockIdx.x * 64;
    const int lr = tid >> 2;        // 0..63 load row
    const int lc = (tid & 3) << 2;  // 0,4,8,12 load col within BK

    const float* Xp = X + (rowBase + lr) * 1024 + lc;
    const float* Wp = W + (colBase + lr) * 1024 + lc;

    float acc[4][4];
    #pragma unroll
    for (int i = 0; i < 4; i++)
        #pragma unroll
        for (int j = 0; j < 4; j++) acc[i][j] = 0.f;

    for (int k0 = 0; k0 < 1024; k0 += 16) {
        float4 xa = *(const float4*)(Xp + k0);
        float4 wa = *(const float4*)(Wp + k0);
        __syncthreads();   // previous tile's reads complete
        Xs[lc+0][lr] = xa.x; Xs[lc+1][lr] = xa.y;
        Xs[lc+2][lr] = xa.z; Xs[lc+3][lr] = xa.w;
        Ws[lc+0][lr] = wa.x; Ws[lc+1][lr] = wa.y;
        Ws[lc+2][lr] = wa.z; Ws[lc+3][lr] = wa.w;
        __syncthreads();
        #pragma unroll
        for (int k = 0; k < 16; k++) {
            float a[4], b[4];
            *(float4*)a = *(const float4*)&Xs[k][ty * 4];
            *(float4*)b = *(const float4*)&Ws[k][tx * 4];
            #pragma unroll
            for (int i = 0; i < 4; i++)
                #pragma unroll
                for (int j = 0; j < 4; j++)
                    acc[i][j] = fmaf(a[i], b[j], acc[i][j]);
        }
    }

    #pragma unroll
    for (int i = 0; i < 4; i++) {
        const int row = rowBase + ty * 4 + i;
        #pragma unroll
        for (int j = 0; j < 4; j++) {
            const int col = colBase + tx * 4 + j;
            Y[row * 1024 + col] = acc[i][j] + bias[col];
        }
    }
}

// ---------------------------------------------------------------------------
// Flash attention (fp32, online softmax), key-padding mask (int32, True=keep).
// Grid: (T/64, H, B). Block 256 threads. Q tile 64 rows x DK=64.
// smem: Qs[64][64] | KtPs[64][68] (K^T, later aliased as P) | Vs[64][64]
// ---------------------------------------------------------------------------
__global__ __launch_bounds__(256) void flash_attn_kernel(
    const float* __restrict__ Q, const float* __restrict__ K,
    const float* __restrict__ V, const int* __restrict__ mask,
    float* __restrict__ Out)
{
    extern __shared__ float sm[];
    float* Qs   = sm;                 // [64][64]
    float* KtPs = sm + 64 * 64;       // [64][68] : Kt[d][c], then Ps[r][s]
    float* Vs   = KtPs + 64 * 68;     // [64][64]

    const int tid = threadIdx.x;
    const int tx = tid & 15;
    const int ty = tid >> 4;
    const int q0 = blockIdx.x * 64;
    const int h  = blockIdx.y;
    const int b  = blockIdx.z;
    const int lr = tid >> 2;          // 0..63
    const int lc = (tid & 3) * 16;    // 0,16,32,48

    // Load Q tile, folding in the 1/sqrt(DK) scale
    {
        const float scale = 0.125f;
        const float* qp = Q + (b * TT + q0 + lr) * DD + h * DK;
        #pragma unroll
        for (int u = 0; u < 4; u++) {
            float4 v = *(const float4*)(qp + lc + u * 4);
            *(float4*)&Qs[lr * 64 + lc + u * 4] =
                make_float4(v.x * scale, v.y * scale, v.z * scale, v.w * scale);
        }
    }

    float m[4], l[4], o[4][4];
    #pragma unroll
    for (int i = 0; i < 4; i++) {
        m[i] = -INFINITY; l[i] = 0.f;
        #pragma unroll
        for (int j = 0; j < 4; j++) o[i][j] = 0.f;
    }

    for (int s0 = 0; s0 < TT; s0 += 64) {
        __syncthreads();  // previous iter's Vs/Ps reads done; also fences Q store
        // Load K (transposed into KtPs) and V
        {
            const float* kp = K + (b * TT + s0 + lr) * DD + h * DK;
            const float* vp = V + (b * TT + s0 + lr) * DD + h * DK;
            #pragma unroll
            for (int u = 0; u < 4; u++) {
                float4 kv = *(const float4*)(kp + lc + u * 4);
                KtPs[(lc + u*4 + 0) * 68 + lr] = kv.x;
                KtPs[(lc + u*4 + 1) * 68 + lr] = kv.y;
                KtPs[(lc + u*4 + 2) * 68 + lr] = kv.z;
                KtPs[(lc + u*4 + 3) * 68 + lr] = kv.w;
                *(float4*)&Vs[lr * 64 + lc + u * 4] = *(const float4*)(vp + lc + u * 4);
            }
        }
        // Mask: int32 per key, nonzero = keep. 4 keys per lane (cols tx*4..tx*4+3).
        const int4 mv = *(const int4*)(mask + b * TT + s0 + tx * 4);
        __syncthreads();

        // Scores: s[i][j] = sum_d Qs[r][d] * Kt[d][c]
        float s[4][4];
        #pragma unroll
        for (int i = 0; i < 4; i++)
            #pragma unroll
            for (int j = 0; j < 4; j++) s[i][j] = 0.f;

        #pragma unroll
        for (int d0 = 0; d0 < 64; d0 += 4) {
            float a[4][4], bb[4][4];
            #pragma unroll
            for (int i = 0; i < 4; i++)
                *(float4*)a[i] = *(const float4*)&Qs[(ty*4 + i) * 64 + d0];
            #pragma unroll
            for (int t = 0; t < 4; t++)
                *(float4*)bb[t] = *(const float4*)&KtPs[(d0 + t) * 68 + tx * 4];
            #pragma unroll
            for (int i = 0; i < 4; i++)
                #pragma unroll
                for (int j = 0; j < 4; j++)
                    #pragma unroll
                    for (int t = 0; t < 4; t++)
                        s[i][j] = fmaf(a[i][t], bb[t][j], s[i][j]);
        }

        // Key-padding mask (nonzero = keep)
        const int mk[4] = {mv.x, mv.y, mv.z, mv.w};
        #pragma unroll
        for (int j = 0; j < 4; j++)
            if (mk[j] == 0) {
                #pragma unroll
                for (int i = 0; i < 4; i++) s[i][j] = -INFINITY;
            }

        // Online softmax per row (row owned by 16 lanes with same ty)
        #pragma unroll
        for (int i = 0; i < 4; i++) {
            float rm = fmaxf(fmaxf(s[i][0], s[i][1]), fmaxf(s[i][2], s[i][3]));
            #pragma unroll
            for (int off = 1; off < 16; off <<= 1)
                rm = fmaxf(rm, __shfl_xor_sync(0xffffffffu, rm, off));
            const float mn = fmaxf(m[i], rm);
            float sc, rs = 0.f;
            if (mn == -INFINITY) {
                sc = 1.f;
                s[i][0] = s[i][1] = s[i][2] = s[i][3] = 0.f;
            } else {
                sc = __expf(m[i] - mn);   // m=-inf -> 0
                #pragma unroll
                for (int j = 0; j < 4; j++) {
                    s[i][j] = __expf(s[i][j] - mn);  // -inf -> 0
                    rs += s[i][j];
                }
            }
            #pragma unroll
            for (int off = 1; off < 16; off <<= 1)
                rs += __shfl_xor_sync(0xffffffffu, rs, off);
            l[i] = l[i] * sc + rs;
            m[i] = mn;
            #pragma unroll
            for (int j = 0; j < 4; j++) o[i][j] *= sc;
        }

        __syncthreads();  // all Kt reads complete before overwrite as P
        #pragma unroll
        for (int i = 0; i < 4; i++)
            *(float4*)&KtPs[(ty*4 + i) * 68 + tx * 4] = *(float4*)s[i];
        __syncthreads();

        // O += P @ V
        #pragma unroll
        for (int ss = 0; ss < 64; ss += 4) {
            float a[4][4], bb[4][4];
            #pragma unroll
            for (int i = 0; i < 4; i++)
                *(float4*)a[i] = *(const float4*)&KtPs[(ty*4 + i) * 68 + ss];
            #pragma unroll
            for (int t = 0; t < 4; t++)
                *(float4*)bb[t] = *(const float4*)&Vs[(ss + t) * 64 + tx * 4];
            #pragma unroll
            for (int i = 0; i < 4; i++)
                #pragma unroll
                for (int j = 0; j < 4; j++)
                    #pragma unroll
                    for (int t = 0; t < 4; t++)
                        o[i][j] = fmaf(a[i][t], bb[t][j], o[i][j]);
        }
    }

    // Epilogue: normalize and write context (interleaved back to [B,T,D])
    #pragma unroll
    for (int i = 0; i < 4; i++) {
        const float inv = 1.f / l[i];
        const int row = b * TT + q0 + ty * 4 + i;
        #pragma unroll
        for (int j = 0; j < 4; j++)
            Out[row * DD + h * DK + tx * 4 + j] = o[i][j] * inv;
    }
}

// ---------------------------------------------------------------------------
extern "C" void kernel_launch(void* const* d_in, const int* in_sizes, int n_in,
                              void* d_out, int out_size)
{
    const float* query = (const float*)d_in[0];
    const float* key   = (const float*)d_in[1];
    const float* value = (const float*)d_in[2];
    const int*   mask  = (const int*)d_in[3];
    const float* Wq = (const float*)d_in[4];
    const float* bq = (const float*)d_in[5];
    const float* Wk = (const float*)d_in[6];
    const float* bk = (const float*)d_in[7];
    const float* Wv = (const float*)d_in[8];
    const float* bv = (const float*)d_in[9];
    const float* Wo = (const float*)d_in[10];
    const float* bo = (const float*)d_in[11];
    float* out = (float*)d_out;

    float *gQ, *gK, *gV, *gC;
    cudaGetSymbolAddress((void**)&gQ, g_Q);
    cudaGetSymbolAddress((void**)&gK, g_K);
    cudaGetSymbolAddress((void**)&gV, g_V);
    cudaGetSymbolAddress((void**)&gC, g_C);

    dim3 ggrid(1024 / 64, 4096 / 64);  // (16, 64)
    gemm_bias_kernel<<<ggrid, 256>>>(query, Wq, bq, gQ);
    gemm_bias_kernel<<<ggrid, 256>>>(key,   Wk, bk, gK);
    gemm_bias_kernel<<<ggrid, 256>>>(value, Wv, bv, gV);

    const int smem = (64*64 + 64*68 + 64*64) * sizeof(float);  // 50176 B
    cudaFuncSetAttribute(flash_attn_kernel,
                         cudaFuncAttributeMaxDynamicSharedMemorySize, smem);
    dim3 fgrid(TT / 64, HH, BB);  // (32, 16, 2)
    flash_attn_kernel<<<fgrid, 256, smem>>>(gQ, gK, gV, mask, gC);

    gemm_bias_kernel<<<ggrid, 256>>>(gC, Wo, bo, out);
}

// round 4
// speedup vs baseline: 1.0118x; 1.0118x over previous
#include <cuda_runtime.h>
#include <math.h>

#define BB 2
#define TT 2048
#define DD 1024
#define HH 16
#define DK 64

typedef unsigned long long u64;

__device__ __forceinline__ u64 pk2(float v) {
    u64 r; asm("mov.b64 %0,{%1,%1};" : "=l"(r) : "f"(v)); return r;
}
__device__ __forceinline__ void fma2(u64& d, u64 a, u64 b) {
    asm("fma.rn.f32x2 %0,%1,%2,%0;" : "+l"(d) : "l"(a), "l"(b));
}
__device__ __forceinline__ void mul2(u64& d, u64 a) {
    asm("mul.rn.f32x2 %0,%1,%2;" : "=l"(d) : "l"(d), "l"(a));
}
__device__ __forceinline__ float lo32(u64 v) { return __uint_as_float((unsigned)v); }
__device__ __forceinline__ float hi32(u64 v) { return __uint_as_float((unsigned)(v >> 32)); }

// Scratch (allocation-free rule: __device__ globals)
__device__ float g_Q[BB*TT*DD];
__device__ float g_K[BB*TT*DD];
__device__ float g_V[BB*TT*DD];
__device__ float g_C[BB*TT*DD];

// ---------------------------------------------------------------------------
// SGEMM: Y[n, m] = sum_k X[n,k] * W[m,k] + bias[m]
// 128x128 CTA tile, BK=16, 256 threads, 8x8 per thread, packed f32x2 FMA.
// ---------------------------------------------------------------------------
__global__ __launch_bounds__(256, 2) void gemm_bias_kernel(
    const float* __restrict__ X, const float* __restrict__ W,
    const float* __restrict__ bias, float* __restrict__ Y)
{
    __shared__ float Xs[16][128];   // [k][row]
    __shared__ float Ws[16][128];   // [k][col]

    const int tid = threadIdx.x;
    const int tx = tid & 15;         // col group
    const int ty = tid >> 4;         // row group
    const int rowBase = blockIdx.y * 128;
    const int colBase = blockIdx.x * 128;
    const int lrow = tid >> 1;       // 0..127
    const int lcg  = (tid & 1) * 8;  // 0 or 8 (k offset)

    const float* Xp = X + (rowBase + lrow) * 1024 + lcg;
    const float* Wp = W + (colBase + lrow) * 1024 + lcg;

    u64 acc[8][4];
    #pragma unroll
    for (int i = 0; i < 8; i++)
        #pragma unroll
        for (int j = 0; j < 4; j++) acc[i][j] = 0ULL;

    for (int k0 = 0; k0 < 1024; k0 += 16) {
        float4 xa0 = *(const float4*)(Xp + k0);
        float4 xa1 = *(const float4*)(Xp + k0 + 4);
        float4 wa0 = *(const float4*)(Wp + k0);
        float4 wa1 = *(const float4*)(Wp + k0 + 4);
        __syncthreads();   // previous tile's reads complete
        Xs[lcg+0][lrow] = xa0.x; Xs[lcg+1][lrow] = xa0.y;
        Xs[lcg+2][lrow] = xa0.z; Xs[lcg+3][lrow] = xa0.w;
        Xs[lcg+4][lrow] = xa1.x; Xs[lcg+5][lrow] = xa1.y;
        Xs[lcg+6][lrow] = xa1.z; Xs[lcg+7][lrow] = xa1.w;
        Ws[lcg+0][lrow] = wa0.x; Ws[lcg+1][lrow] = wa0.y;
        Ws[lcg+2][lrow] = wa0.z; Ws[lcg+3][lrow] = wa0.w;
        Ws[lcg+4][lrow] = wa1.x; Ws[lcg+5][lrow] = wa1.y;
        Ws[lcg+6][lrow] = wa1.z; Ws[lcg+7][lrow] = wa1.w;
        __syncthreads();

        #pragma unroll
        for (int k = 0; k < 16; k++) {
            float a[8];
            *(float4*)&a[0] = *(const float4*)&Xs[k][ty * 8];
            *(float4*)&a[4] = *(const float4*)&Xs[k][ty * 8 + 4];
            ulonglong2 b0 = *(const ulonglong2*)&Ws[k][tx * 8];
            ulonglong2 b1 = *(const ulonglong2*)&Ws[k][tx * 8 + 4];
            #pragma unroll
            for (int i = 0; i < 8; i++) {
                u64 ad = pk2(a[i]);
                fma2(acc[i][0], ad, b0.x);
                fma2(acc[i][1], ad, b0.y);
                fma2(acc[i][2], ad, b1.x);
                fma2(acc[i][3], ad, b1.y);
            }
        }
    }

    float bcol[8];
    *(float4*)&bcol[0] = *(const float4*)&bias[colBase + tx * 8];
    *(float4*)&bcol[4] = *(const float4*)&bias[colBase + tx * 8 + 4];
    #pragma unroll
    for (int i = 0; i < 8; i++) {
        const int row = rowBase + ty * 8 + i;
        float4 v0 = make_float4(lo32(acc[i][0]) + bcol[0], hi32(acc[i][0]) + bcol[1],
                                lo32(acc[i][1]) + bcol[2], hi32(acc[i][1]) + bcol[3]);
        float4 v1 = make_float4(lo32(acc[i][2]) + bcol[4], hi32(acc[i][2]) + bcol[5],
                                lo32(acc[i][3]) + bcol[6], hi32(acc[i][3]) + bcol[7]);
        *(float4*)&Y[row * 1024 + colBase + tx * 8] = v0;
        *(float4*)&Y[row * 1024 + colBase + tx * 8 + 4] = v1;
    }
}

// ---------------------------------------------------------------------------
// Flash attention fp32, packed f32x2 FMA. Q-tile 128 rows, key-tile 128.
// 256 threads; scores 8x8/thread, PV 8x4/thread. mask int32 (nonzero=keep).
// smem: Qt[64][132] | KtP[128][132] (K^T rows 0..63, then P^T[key][row]) | Vs[128][64]
// ---------------------------------------------------------------------------
#define QT_OFF   0
#define KTP_OFF  (64 * 132)
#define VS_OFF   (64 * 132 + 128 * 132)
#define SM_FLOATS (64 * 132 + 128 * 132 + 128 * 64)

__global__ __launch_bounds__(256, 1) void flash_attn_kernel(
    const float* __restrict__ Q, const float* __restrict__ K,
    const float* __restrict__ V, const int* __restrict__ mask,
    float* __restrict__ Out)
{
    extern __shared__ float sm[];
    float* Qt  = sm + QT_OFF;    // [d][row]   stride 132
    float* KtP = sm + KTP_OFF;   // Kt: [d][key] / Pt: [key][row], stride 132
    float* Vs  = sm + VS_OFF;    // [key][d]   stride 64

    const int tid = threadIdx.x;
    const int tx = tid & 15;
    const int ty = tid >> 4;
    const int q0 = blockIdx.x * 128;
    const int h  = blockIdx.y;
    const int b  = blockIdx.z;
    const int lr4 = tid >> 2;        // 0..63
    const int lc4 = (tid & 3) * 16;  // 0,16,32,48

    // Load Q tile transposed + scaled: Qt[d][row]
    {
        const float scale = 0.125f;
        #pragma unroll
        for (int r0 = 0; r0 < 128; r0 += 64) {
            const int row = r0 + lr4;
            const float* qp = Q + (b * TT + q0 + row) * DD + h * DK + lc4;
            #pragma unroll
            for (int u = 0; u < 4; u++) {
                float4 v = *(const float4*)(qp + u * 4);
                const int d = lc4 + u * 4;
                Qt[(d+0)*132 + row] = v.x * scale;
                Qt[(d+1)*132 + row] = v.y * scale;
                Qt[(d+2)*132 + row] = v.z * scale;
                Qt[(d+3)*132 + row] = v.w * scale;
            }
        }
    }

    float m[8], l[8];
    u64 o2[8][2];
    #pragma unroll
    for (int i = 0; i < 8; i++) {
        m[i] = -INFINITY; l[i] = 0.f;
        o2[i][0] = 0ULL; o2[i][1] = 0ULL;
    }

    for (int s0 = 0; s0 < TT; s0 += 128) {
        __syncthreads();  // prior iter's Pt/Vs reads done; also fences Qt store
        // K tile transposed: Kt[d][key]; V tile direct: Vs[key][d]
        #pragma unroll
        for (int kk = 0; kk < 128; kk += 64) {
            const int key = kk + lr4;
            const float* kp = K + (b * TT + s0 + key) * DD + h * DK + lc4;
            const float* vp = V + (b * TT + s0 + key) * DD + h * DK + lc4;
            #pragma unroll
            for (int u = 0; u < 4; u++) {
                float4 kv = *(const float4*)(kp + u * 4);
                const int d = lc4 + u * 4;
                KtP[(d+0)*132 + key] = kv.x;
                KtP[(d+1)*132 + key] = kv.y;
                KtP[(d+2)*132 + key] = kv.z;
                KtP[(d+3)*132 + key] = kv.w;
                *(float4*)&Vs[key * 64 + d] = *(const float4*)(vp + u * 4);
            }
        }
        const int4 m0 = *(const int4*)(mask + b * TT + s0 + tx * 8);
        const int4 m1 = *(const int4*)(mask + b * TT + s0 + tx * 8 + 4);
        __syncthreads();

        // Scores: s2[i][p] over keys tx*8.. , rows ty*8..
        u64 s2[8][4];
        #pragma unroll
        for (int i = 0; i < 8; i++)
            #pragma unroll
            for (int p = 0; p < 4; p++) s2[i][p] = 0ULL;

        #pragma unroll 8
        for (int d = 0; d < 64; d++) {
            float a[8];
            *(float4*)&a[0] = *(const float4*)&Qt[d * 132 + ty * 8];
            *(float4*)&a[4] = *(const float4*)&Qt[d * 132 + ty * 8 + 4];
            ulonglong2 b0 = *(const ulonglong2*)&KtP[d * 132 + tx * 8];
            ulonglong2 b1 = *(const ulonglong2*)&KtP[d * 132 + tx * 8 + 4];
            #pragma unroll
            for (int i = 0; i < 8; i++) {
                u64 ad = pk2(a[i]);
                fma2(s2[i][0], ad, b0.x);
                fma2(s2[i][1], ad, b0.y);
                fma2(s2[i][2], ad, b1.x);
                fma2(s2[i][3], ad, b1.y);
            }
        }

        // Unpack + mask
        float s[8][8];
        #pragma unroll
        for (int i = 0; i < 8; i++)
            #pragma unroll
            for (int p = 0; p < 4; p++) {
                s[i][2*p]   = lo32(s2[i][p]);
                s[i][2*p+1] = hi32(s2[i][p]);
            }
        const int mk[8] = {m0.x, m0.y, m0.z, m0.w, m1.x, m1.y, m1.z, m1.w};
        #pragma unroll
        for (int j = 0; j < 8; j++)
            if (mk[j] == 0) {
                #pragma unroll
                for (int i = 0; i < 8; i++) s[i][j] = -INFINITY;
            }

        // Online softmax (row spread across 16 lanes with same ty)
        #pragma unroll
        for (int i = 0; i < 8; i++) {
            float rm = s[i][0];
            #pragma unroll
            for (int j = 1; j < 8; j++) rm = fmaxf(rm, s[i][j]);
            #pragma unroll
            for (int off = 1; off < 16; off <<= 1)
                rm = fmaxf(rm, __shfl_xor_sync(0xffffffffu, rm, off));
            const float mn = fmaxf(m[i], rm);
            float sc, rs = 0.f;
            if (mn == -INFINITY) {
                sc = 1.f;
                #pragma unroll
                for (int j = 0; j < 8; j++) s[i][j] = 0.f;
            } else {
                sc = __expf(m[i] - mn);
                #pragma unroll
                for (int j = 0; j < 8; j++) {
                    s[i][j] = __expf(s[i][j] - mn);
                    rs += s[i][j];
                }
            }
            #pragma unroll
            for (int off = 1; off < 16; off <<= 1)
                rs += __shfl_xor_sync(0xffffffffu, rs, off);
            l[i] = l[i] * sc + rs;
            m[i] = mn;
            const u64 scd = pk2(sc);
            mul2(o2[i][0], scd);
            mul2(o2[i][1], scd);
        }

        __syncthreads();  // all Kt reads done before Pt overwrite
        // Store P transposed: Pt[key][row]
        #pragma unroll
        for (int j = 0; j < 8; j++) {
            const int key = tx * 8 + j;
            float4 v0 = make_float4(s[0][j], s[1][j], s[2][j], s[3][j]);
            float4 v1 = make_float4(s[4][j], s[5][j], s[6][j], s[7][j]);
            *(float4*)&KtP[key * 132 + ty * 8]     = v0;
            *(float4*)&KtP[key * 132 + ty * 8 + 4] = v1;
        }
        __syncthreads();

        // O += P^T-gathered: o[i][d] += Pt[sk][row_i] * Vs[sk][d]
        #pragma unroll 8
        for (int sk = 0; sk < 128; sk++) {
            float a[8];
            *(float4*)&a[0] = *(const float4*)&KtP[sk * 132 + ty * 8];
            *(float4*)&a[4] = *(const float4*)&KtP[sk * 132 + ty * 8 + 4];
            ulonglong2 bv = *(const ulonglong2*)&Vs[sk * 64 + tx * 4];
            #pragma unroll
            for (int i = 0; i < 8; i++) {
                u64 ad = pk2(a[i]);
                fma2(o2[i][0], ad, bv.x);
                fma2(o2[i][1], ad, bv.y);
            }
        }
    }

    // Epilogue: normalize, write [B,T,D] interleaved
    #pragma unroll
    for (int i = 0; i < 8; i++) {
        const float inv = 1.f / l[i];
        const int row = b * TT + q0 + ty * 8 + i;
        float4 v = make_float4(lo32(o2[i][0]) * inv, hi32(o2[i][0]) * inv,
                               lo32(o2[i][1]) * inv, hi32(o2[i][1]) * inv);
        *(float4*)&Out[row * DD + h * DK + tx * 4] = v;
    }
}

// ---------------------------------------------------------------------------
extern "C" void kernel_launch(void* const* d_in, const int* in_sizes, int n_in,
                              void* d_out, int out_size)
{
    const float* query = (const float*)d_in[0];
    const float* key   = (const float*)d_in[1];
    const float* value = (const float*)d_in[2];
    const int*   mask  = (const int*)d_in[3];
    const float* Wq = (const float*)d_in[4];
    const float* bq = (const float*)d_in[5];
    const float* Wk = (const float*)d_in[6];
    const float* bk = (const float*)d_in[7];
    const float* Wv = (const float*)d_in[8];
    const float* bv = (const float*)d_in[9];
    const float* Wo = (const float*)d_in[10];
    const float* bo = (const float*)d_in[11];
    float* out = (float*)d_out;

    float *gQ, *gK, *gV, *gC;
    cudaGetSymbolAddress((void**)&gQ, g_Q);
    cudaGetSymbolAddress((void**)&gK, g_K);
    cudaGetSymbolAddress((void**)&gV, g_V);
    cudaGetSymbolAddress((void**)&gC, g_C);

    dim3 ggrid(1024 / 128, 4096 / 128);  // (8, 32)
    gemm_bias_kernel<<<ggrid, 256>>>(query, Wq, bq, gQ);
    gemm_bias_kernel<<<ggrid, 256>>>(key,   Wk, bk, gK);
    gemm_bias_kernel<<<ggrid, 256>>>(value, Wv, bv, gV);

    const int smem = SM_FLOATS * sizeof(float);  // 134144 B
    cudaFuncSetAttribute(flash_attn_kernel,
                         cudaFuncAttributeMaxDynamicSharedMemorySize, smem);
    dim3 fgrid(TT / 128, HH, BB);  // (16, 16, 2)
    flash_attn_kernel<<<fgrid, 256, smem>>>(gQ, gK, gV, mask, gC);

    gemm_bias_kernel<<<ggrid, 256>>>(gC, Wo, bo, out);
}

// round 5
// speedup vs baseline: 1.1751x; 1.1614x over previous
#include <cuda_runtime.h>
#include <cuda_bf16.h>
#include <math.h>

#define BB 2
#define TT 2048
#define DD 1024
#define HH 16
#define DK 64

typedef unsigned long long u64;
typedef unsigned int u32;

__device__ __forceinline__ u64 pk2(float v) {
    u64 r; asm("mov.b64 %0,{%1,%1};" : "=l"(r) : "f"(v)); return r;
}
__device__ __forceinline__ void fma2(u64& d, u64 a, u64 b) {
    asm("fma.rn.f32x2 %0,%1,%2,%0;" : "+l"(d) : "l"(a), "l"(b));
}
__device__ __forceinline__ void mul2(u64& d, u64 a) {
    asm("mul.rn.f32x2 %0,%1,%2;" : "=l"(d) : "l"(d), "l"(a));
}
__device__ __forceinline__ float lo32(u64 v) { return __uint_as_float((unsigned)v); }
__device__ __forceinline__ float hi32(u64 v) { return __uint_as_float((unsigned)(v >> 32)); }

__device__ __forceinline__ void ldmx4(u32& r0, u32& r1, u32& r2, u32& r3, const void* p) {
    u32 addr = (u32)__cvta_generic_to_shared(p);
    asm volatile("ldmatrix.sync.aligned.m8n8.x4.shared.b16 {%0,%1,%2,%3},[%4];"
                 : "=r"(r0), "=r"(r1), "=r"(r2), "=r"(r3) : "r"(addr));
}
__device__ __forceinline__ void mma16816(float* c, const u32* a, const u32* b) {
    asm volatile(
        "mma.sync.aligned.m16n8k16.row.col.f32.bf16.bf16.f32 "
        "{%0,%1,%2,%3},{%4,%5,%6,%7},{%8,%9},{%0,%1,%2,%3};"
        : "+f"(c[0]), "+f"(c[1]), "+f"(c[2]), "+f"(c[3])
        : "r"(a[0]), "r"(a[1]), "r"(a[2]), "r"(a[3]), "r"(b[0]), "r"(b[1]));
}

// Scratch (allocation-free rule: __device__ globals)
__device__ float g_Q[BB*TT*DD];
__device__ float g_K[BB*TT*DD];
__device__ float g_V[BB*TT*DD];
__device__ float g_C[BB*TT*DD];

// ---------------------------------------------------------------------------
// Tensor-core SGEMM via bf16 hi/lo split (3 MMAs): Y = X @ W^T + bias.
// X:[4096,1024], W:[1024,1024] row-major (k-major both). CTA 128x128, BK=32,
// 8 warps each 32(rows)x64(cols). fp32->bf16 hi/lo conversion in smem.
// ---------------------------------------------------------------------------
#define GW 40   // smem k-stride in bf16 units (80B, 16B-aligned, LDSM conflict-free)

__global__ __launch_bounds__(256, 1) void gemm_bias_tc(
    const float* __restrict__ X, const float* __restrict__ W,
    const float* __restrict__ bias, float* __restrict__ Y)
{
    __shared__ __nv_bfloat16 Ah[128][GW], Al[128][GW], Bh[128][GW], Bl[128][GW];

    const int tid  = threadIdx.x;
    const int lane = tid & 31;
    const int warp = tid >> 5;
    const int wr = (warp & 3) * 32;   // warp row base within CTA tile
    const int wc = (warp >> 2) * 64;  // warp col base within CTA tile
    const int rowBase = blockIdx.y * 128;
    const int colBase = blockIdx.x * 128;

    const int lrow = tid >> 1;        // 0..127 (load row)
    const int lk   = (tid & 1) * 16;  // 0 or 16 (k offset)

    const float* Xp = X + (rowBase + lrow) * 1024 + lk;
    const float* Wp = W + (colBase + lrow) * 1024 + lk;

    // ldmatrix source addresses (per lane)
    const int a_r = (lane & 15);
    const int a_k = (lane >> 4) * 8;
    const int b_r = ((lane >> 4) << 3) + (lane & 7);
    const int b_k = ((lane >> 3) & 1) * 8;

    float acc[2][8][4];
    #pragma unroll
    for (int mt = 0; mt < 2; mt++)
        #pragma unroll
        for (int nt = 0; nt < 8; nt++)
            #pragma unroll
            for (int q = 0; q < 4; q++) acc[mt][nt][q] = 0.f;

    for (int k0 = 0; k0 < 1024; k0 += 32) {
        float4 xv[4], wv[4];
        #pragma unroll
        for (int u = 0; u < 4; u++) {
            xv[u] = *(const float4*)(Xp + k0 + u * 4);
            wv[u] = *(const float4*)(Wp + k0 + u * 4);
        }
        __syncthreads();   // previous iteration's frag reads complete
        #pragma unroll
        for (int u = 0; u < 4; u++) {
            const float fx[4] = {xv[u].x, xv[u].y, xv[u].z, xv[u].w};
            const float fw[4] = {wv[u].x, wv[u].y, wv[u].z, wv[u].w};
            #pragma unroll
            for (int e = 0; e < 4; e += 2) {
                __nv_bfloat16 h0 = __float2bfloat16(fx[e]);
                __nv_bfloat16 h1 = __float2bfloat16(fx[e+1]);
                __nv_bfloat16 l0 = __float2bfloat16(fx[e]   - __bfloat162float(h0));
                __nv_bfloat16 l1 = __float2bfloat16(fx[e+1] - __bfloat162float(h1));
                *(__nv_bfloat162*)&Ah[lrow][lk + u*4 + e] = __nv_bfloat162(h0, h1);
                *(__nv_bfloat162*)&Al[lrow][lk + u*4 + e] = __nv_bfloat162(l0, l1);
                __nv_bfloat16 g0 = __float2bfloat16(fw[e]);
                __nv_bfloat16 g1 = __float2bfloat16(fw[e+1]);
                __nv_bfloat16 m0 = __float2bfloat16(fw[e]   - __bfloat162float(g0));
                __nv_bfloat16 m1 = __float2bfloat16(fw[e+1] - __bfloat162float(g1));
                *(__nv_bfloat162*)&Bh[lrow][lk + u*4 + e] = __nv_bfloat162(g0, g1);
                *(__nv_bfloat162*)&Bl[lrow][lk + u*4 + e] = __nv_bfloat162(m0, m1);
            }
        }
        __syncthreads();

        #pragma unroll
        for (int ks = 0; ks < 32; ks += 16) {
            u32 ah[2][4], al[2][4], bh[4][4], bl[4][4];
            #pragma unroll
            for (int mt = 0; mt < 2; mt++) {
                ldmx4(ah[mt][0], ah[mt][1], ah[mt][2], ah[mt][3],
                      &Ah[wr + mt*16 + a_r][ks + a_k]);
                ldmx4(al[mt][0], al[mt][1], al[mt][2], al[mt][3],
                      &Al[wr + mt*16 + a_r][ks + a_k]);
            }
            #pragma unroll
            for (int p = 0; p < 4; p++) {
                ldmx4(bh[p][0], bh[p][1], bh[p][2], bh[p][3],
                      &Bh[wc + p*16 + b_r][ks + b_k]);
                ldmx4(bl[p][0], bl[p][1], bl[p][2], bl[p][3],
                      &Bl[wc + p*16 + b_r][ks + b_k]);
            }
            #pragma unroll
            for (int mt = 0; mt < 2; mt++)
                #pragma unroll
                for (int nt = 0; nt < 8; nt++) {
                    const u32* bhp = &bh[nt >> 1][(nt & 1) * 2];
                    const u32* blp = &bl[nt >> 1][(nt & 1) * 2];
                    mma16816(acc[mt][nt], ah[mt], bhp);
                    mma16816(acc[mt][nt], ah[mt], blp);
                    mma16816(acc[mt][nt], al[mt], bhp);
                }
        }
    }

    // Epilogue: c0,c1 -> (row, col..col+1); c2,c3 -> (row+8, col..col+1)
    const int crow = rowBase + wr + (lane >> 2);
    const int ccol = colBase + wc + (lane & 3) * 2;
    #pragma unroll
    for (int mt = 0; mt < 2; mt++)
        #pragma unroll
        for (int nt = 0; nt < 8; nt++) {
            const int row = crow + mt * 16;
            const int col = ccol + nt * 8;
            const float b0 = bias[col], b1 = bias[col + 1];
            Y[row * 1024 + col]           = acc[mt][nt][0] + b0;
            Y[row * 1024 + col + 1]       = acc[mt][nt][1] + b1;
            Y[(row + 8) * 1024 + col]     = acc[mt][nt][2] + b0;
            Y[(row + 8) * 1024 + col + 1] = acc[mt][nt][3] + b1;
        }
}

// ---------------------------------------------------------------------------
// Flash attention fp32, packed f32x2 FMA. Q-tile 128 rows, key-tile 128.
// (unchanged from R4)
// ---------------------------------------------------------------------------
#define QT_OFF   0
#define KTP_OFF  (64 * 132)
#define VS_OFF   (64 * 132 + 128 * 132)
#define SM_FLOATS (64 * 132 + 128 * 132 + 128 * 64)

__global__ __launch_bounds__(256, 1) void flash_attn_kernel(
    const float* __restrict__ Q, const float* __restrict__ K,
    const float* __restrict__ V, const int* __restrict__ mask,
    float* __restrict__ Out)
{
    extern __shared__ float sm[];
    float* Qt  = sm + QT_OFF;    // [d][row]   stride 132
    float* KtP = sm + KTP_OFF;   // Kt: [d][key] / Pt: [key][row], stride 132
    float* Vs  = sm + VS_OFF;    // [key][d]   stride 64

    const int tid = threadIdx.x;
    const int tx = tid & 15;
    const int ty = tid >> 4;
    const int q0 = blockIdx.x * 128;
    const int h  = blockIdx.y;
    const int b  = blockIdx.z;
    const int lr4 = tid >> 2;        // 0..63
    const int lc4 = (tid & 3) * 16;  // 0,16,32,48

    {
        const float scale = 0.125f;
        #pragma unroll
        for (int r0 = 0; r0 < 128; r0 += 64) {
            const int row = r0 + lr4;
            const float* qp = Q + (b * TT + q0 + row) * DD + h * DK + lc4;
            #pragma unroll
            for (int u = 0; u < 4; u++) {
                float4 v = *(const float4*)(qp + u * 4);
                const int d = lc4 + u * 4;
                Qt[(d+0)*132 + row] = v.x * scale;
                Qt[(d+1)*132 + row] = v.y * scale;
                Qt[(d+2)*132 + row] = v.z * scale;
                Qt[(d+3)*132 + row] = v.w * scale;
            }
        }
    }

    float m[8], l[8];
    u64 o2[8][2];
    #pragma unroll
    for (int i = 0; i < 8; i++) {
        m[i] = -INFINITY; l[i] = 0.f;
        o2[i][0] = 0ULL; o2[i][1] = 0ULL;
    }

    for (int s0 = 0; s0 < TT; s0 += 128) {
        __syncthreads();
        #pragma unroll
        for (int kk = 0; kk < 128; kk += 64) {
            const int key = kk + lr4;
            const float* kp = K + (b * TT + s0 + key) * DD + h * DK + lc4;
            const float* vp = V + (b * TT + s0 + key) * DD + h * DK + lc4;
            #pragma unroll
            for (int u = 0; u < 4; u++) {
                float4 kv = *(const float4*)(kp + u * 4);
                const int d = lc4 + u * 4;
                KtP[(d+0)*132 + key] = kv.x;
                KtP[(d+1)*132 + key] = kv.y;
                KtP[(d+2)*132 + key] = kv.z;
                KtP[(d+3)*132 + key] = kv.w;
                *(float4*)&Vs[key * 64 + d] = *(const float4*)(vp + u * 4);
            }
        }
        const int4 m0 = *(const int4*)(mask + b * TT + s0 + tx * 8);
        const int4 m1 = *(const int4*)(mask + b * TT + s0 + tx * 8 + 4);
        __syncthreads();

        u64 s2[8][4];
        #pragma unroll
        for (int i = 0; i < 8; i++)
            #pragma unroll
            for (int p = 0; p < 4; p++) s2[i][p] = 0ULL;

        #pragma unroll 8
        for (int d = 0; d < 64; d++) {
            float a[8];
            *(float4*)&a[0] = *(const float4*)&Qt[d * 132 + ty * 8];
            *(float4*)&a[4] = *(const float4*)&Qt[d * 132 + ty * 8 + 4];
            ulonglong2 b0 = *(const ulonglong2*)&KtP[d * 132 + tx * 8];
            ulonglong2 b1 = *(const ulonglong2*)&KtP[d * 132 + tx * 8 + 4];
            #pragma unroll
            for (int i = 0; i < 8; i++) {
                u64 ad = pk2(a[i]);
                fma2(s2[i][0], ad, b0.x);
                fma2(s2[i][1], ad, b0.y);
                fma2(s2[i][2], ad, b1.x);
                fma2(s2[i][3], ad, b1.y);
            }
        }

        float s[8][8];
        #pragma unroll
        for (int i = 0; i < 8; i++)
            #pragma unroll
            for (int p = 0; p < 4; p++) {
                s[i][2*p]   = lo32(s2[i][p]);
                s[i][2*p+1] = hi32(s2[i][p]);
            }
        const int mk[8] = {m0.x, m0.y, m0.z, m0.w, m1.x, m1.y, m1.z, m1.w};
        #pragma unroll
        for (int j = 0; j < 8; j++)
            if (mk[j] == 0) {
                #pragma unroll
                for (int i = 0; i < 8; i++) s[i][j] = -INFINITY;
            }

        #pragma unroll
        for (int i = 0; i < 8; i++) {
            float rm = s[i][0];
            #pragma unroll
            for (int j = 1; j < 8; j++) rm = fmaxf(rm, s[i][j]);
            #pragma unroll
            for (int off = 1; off < 16; off <<= 1)
                rm = fmaxf(rm, __shfl_xor_sync(0xffffffffu, rm, off));
            const float mn = fmaxf(m[i], rm);
            float sc, rs = 0.f;
            if (mn == -INFINITY) {
                sc = 1.f;
                #pragma unroll
                for (int j = 0; j < 8; j++) s[i][j] = 0.f;
            } else {
                sc = __expf(m[i] - mn);
                #pragma unroll
                for (int j = 0; j < 8; j++) {
                    s[i][j] = __expf(s[i][j] - mn);
                    rs += s[i][j];
                }
            }
            #pragma unroll
            for (int off = 1; off < 16; off <<= 1)
                rs += __shfl_xor_sync(0xffffffffu, rs, off);
            l[i] = l[i] * sc + rs;
            m[i] = mn;
            const u64 scd = pk2(sc);
            mul2(o2[i][0], scd);
            mul2(o2[i][1], scd);
        }

        __syncthreads();
        #pragma unroll
        for (int j = 0; j < 8; j++) {
            const int key = tx * 8 + j;
            float4 v0 = make_float4(s[0][j], s[1][j], s[2][j], s[3][j]);
            float4 v1 = make_float4(s[4][j], s[5][j], s[6][j], s[7][j]);
            *(float4*)&KtP[key * 132 + ty * 8]     = v0;
            *(float4*)&KtP[key * 132 + ty * 8 + 4] = v1;
        }
        __syncthreads();

        #pragma unroll 8
        for (int sk = 0; sk < 128; sk++) {
            float a[8];
            *(float4*)&a[0] = *(const float4*)&KtP[sk * 132 + ty * 8];
            *(float4*)&a[4] = *(const float4*)&KtP[sk * 132 + ty * 8 + 4];
            ulonglong2 bv = *(const ulonglong2*)&Vs[sk * 64 + tx * 4];
            #pragma unroll
            for (int i = 0; i < 8; i++) {
                u64 ad = pk2(a[i]);
                fma2(o2[i][0], ad, bv.x);
                fma2(o2[i][1], ad, bv.y);
            }
        }
    }

    #pragma unroll
    for (int i = 0; i < 8; i++) {
        const float inv = 1.f / l[i];
        const int row = b * TT + q0 + ty * 8 + i;
        float4 v = make_float4(lo32(o2[i][0]) * inv, hi32(o2[i][0]) * inv,
                               lo32(o2[i][1]) * inv, hi32(o2[i][1]) * inv);
        *(float4*)&Out[row * DD + h * DK + tx * 4] = v;
    }
}

// ---------------------------------------------------------------------------
extern "C" void kernel_launch(void* const* d_in, const int* in_sizes, int n_in,
                              void* d_out, int out_size)
{
    const float* query = (const float*)d_in[0];
    const float* key   = (const float*)d_in[1];
    const float* value = (const float*)d_in[2];
    const int*   mask  = (const int*)d_in[3];
    const float* Wq = (const float*)d_in[4];
    const float* bq = (const float*)d_in[5];
    const float* Wk = (const float*)d_in[6];
    const float* bk = (const float*)d_in[7];
    const float* Wv = (const float*)d_in[8];
    const float* bv = (const float*)d_in[9];
    const float* Wo = (const float*)d_in[10];
    const float* bo = (const float*)d_in[11];
    float* out = (float*)d_out;

    float *gQ, *gK, *gV, *gC;
    cudaGetSymbolAddress((void**)&gQ, g_Q);
    cudaGetSymbolAddress((void**)&gK, g_K);
    cudaGetSymbolAddress((void**)&gV, g_V);
    cudaGetSymbolAddress((void**)&gC, g_C);

    dim3 ggrid(1024 / 128, 4096 / 128);  // (8, 32)
    gemm_bias_tc<<<ggrid, 256>>>(query, Wq, bq, gQ);
    gemm_bias_tc<<<ggrid, 256>>>(key,   Wk, bk, gK);
    gemm_bias_tc<<<ggrid, 256>>>(value, Wv, bv, gV);

    const int smem = SM_FLOATS * sizeof(float);  // 134144 B
    cudaFuncSetAttribute(flash_attn_kernel,
                         cudaFuncAttributeMaxDynamicSharedMemorySize, smem);
    dim3 fgrid(TT / 128, HH, BB);  // (16, 16, 2)
    flash_attn_kernel<<<fgrid, 256, smem>>>(gQ, gK, gV, mask, gC);

    gemm_bias_tc<<<ggrid, 256>>>(gC, Wo, bo, out);
}

// round 6
// speedup vs baseline: 1.8241x; 1.5523x over previous
#include <cuda_runtime.h>
#include <cuda_bf16.h>
#include <math.h>

#define BB 2
#define TT 2048
#define DD 1024
#define HH 16
#define DK 64

typedef unsigned long long u64;
typedef unsigned int u32;

__device__ __forceinline__ void ldmx4(u32& r0, u32& r1, u32& r2, u32& r3, const void* p) {
    u32 addr = (u32)__cvta_generic_to_shared(p);
    asm volatile("ldmatrix.sync.aligned.m8n8.x4.shared.b16 {%0,%1,%2,%3},[%4];"
                 : "=r"(r0), "=r"(r1), "=r"(r2), "=r"(r3) : "r"(addr));
}
__device__ __forceinline__ void ldmx4t(u32& r0, u32& r1, u32& r2, u32& r3, const void* p) {
    u32 addr = (u32)__cvta_generic_to_shared(p);
    asm volatile("ldmatrix.sync.aligned.m8n8.x4.trans.shared.b16 {%0,%1,%2,%3},[%4];"
                 : "=r"(r0), "=r"(r1), "=r"(r2), "=r"(r3) : "r"(addr));
}
__device__ __forceinline__ void mma16816(float* c, const u32* a, const u32* b) {
    asm volatile(
        "mma.sync.aligned.m16n8k16.row.col.f32.bf16.bf16.f32 "
        "{%0,%1,%2,%3},{%4,%5,%6,%7},{%8,%9},{%0,%1,%2,%3};"
        : "+f"(c[0]), "+f"(c[1]), "+f"(c[2]), "+f"(c[3])
        : "r"(a[0]), "r"(a[1]), "r"(a[2]), "r"(a[3]), "r"(b[0]), "r"(b[1]));
}
// pack two f32 -> bf16x2 (lo in low half)
__device__ __forceinline__ u32 packbf(float lo, float hi) {
    u32 r; asm("cvt.rn.satfinite.bf16x2.f32 %0,%1,%2;" : "=r"(r) : "f"(hi), "f"(lo));
    return r;
}
// MUFU-free exp: 2^(x*log2e), magic-number rounding, deg-5 poly. x <= ~0.
__device__ __forceinline__ float fast_exp(float x) {
    float z = fmaxf(x * 1.4426950408889634f, -126.0f);
    float zi = z + 12582912.0f;                 // round-to-nearest integer
    float f = z - (zi - 12582912.0f);           // frac in [-0.5, 0.5]
    int n = __float_as_int(zi) - 0x4B400000;    // integer part
    float p = 1.3333558e-3f;
    p = fmaf(p, f, 9.6181291e-3f);
    p = fmaf(p, f, 5.5504109e-2f);
    p = fmaf(p, f, 2.4022651e-1f);
    p = fmaf(p, f, 6.9314718e-1f);
    p = fmaf(p, f, 1.0f);
    return p * __int_as_float((n + 127) << 23);
}

// Scratch (allocation-free rule: __device__ globals)
__device__ float g_Q[BB*TT*DD];
__device__ float g_K[BB*TT*DD];
__device__ float g_V[BB*TT*DD];
__device__ float g_C[BB*TT*DD];

// ---------------------------------------------------------------------------
// Tensor-core SGEMM via bf16 hi/lo split (3 MMAs): Y = X @ W^T + bias.
// (unchanged from R5)
// ---------------------------------------------------------------------------
#define GW 40

__global__ __launch_bounds__(256, 1) void gemm_bias_tc(
    const float* __restrict__ X, const float* __restrict__ W,
    const float* __restrict__ bias, float* __restrict__ Y)
{
    __shared__ __nv_bfloat16 Ah[128][GW], Al[128][GW], Bh[128][GW], Bl[128][GW];

    const int tid  = threadIdx.x;
    const int lane = tid & 31;
    const int warp = tid >> 5;
    const int wr = (warp & 3) * 32;
    const int wc = (warp >> 2) * 64;
    const int rowBase = blockIdx.y * 128;
    const int colBase = blockIdx.x * 128;

    const int lrow = tid >> 1;
    const int lk   = (tid & 1) * 16;

    const float* Xp = X + (rowBase + lrow) * 1024 + lk;
    const float* Wp = W + (colBase + lrow) * 1024 + lk;

    const int a_r = (lane & 15);
    const int a_k = (lane >> 4) * 8;
    const int b_r = ((lane >> 4) << 3) + (lane & 7);
    const int b_k = ((lane >> 3) & 1) * 8;

    float acc[2][8][4];
    #pragma unroll
    for (int mt = 0; mt < 2; mt++)
        #pragma unroll
        for (int nt = 0; nt < 8; nt++)
            #pragma unroll
            for (int q = 0; q < 4; q++) acc[mt][nt][q] = 0.f;

    for (int k0 = 0; k0 < 1024; k0 += 32) {
        float4 xv[4], wv[4];
        #pragma unroll
        for (int u = 0; u < 4; u++) {
            xv[u] = *(const float4*)(Xp + k0 + u * 4);
            wv[u] = *(const float4*)(Wp + k0 + u * 4);
        }
        __syncthreads();
        #pragma unroll
        for (int u = 0; u < 4; u++) {
            const float fx[4] = {xv[u].x, xv[u].y, xv[u].z, xv[u].w};
            const float fw[4] = {wv[u].x, wv[u].y, wv[u].z, wv[u].w};
            #pragma unroll
            for (int e = 0; e < 4; e += 2) {
                __nv_bfloat16 h0 = __float2bfloat16(fx[e]);
                __nv_bfloat16 h1 = __float2bfloat16(fx[e+1]);
                __nv_bfloat16 l0 = __float2bfloat16(fx[e]   - __bfloat162float(h0));
                __nv_bfloat16 l1 = __float2bfloat16(fx[e+1] - __bfloat162float(h1));
                *(__nv_bfloat162*)&Ah[lrow][lk + u*4 + e] = __nv_bfloat162(h0, h1);
                *(__nv_bfloat162*)&Al[lrow][lk + u*4 + e] = __nv_bfloat162(l0, l1);
                __nv_bfloat16 g0 = __float2bfloat16(fw[e]);
                __nv_bfloat16 g1 = __float2bfloat16(fw[e+1]);
                __nv_bfloat16 m0 = __float2bfloat16(fw[e]   - __bfloat162float(g0));
                __nv_bfloat16 m1 = __float2bfloat16(fw[e+1] - __bfloat162float(g1));
                *(__nv_bfloat162*)&Bh[lrow][lk + u*4 + e] = __nv_bfloat162(g0, g1);
                *(__nv_bfloat162*)&Bl[lrow][lk + u*4 + e] = __nv_bfloat162(m0, m1);
            }
        }
        __syncthreads();

        #pragma unroll
        for (int ks = 0; ks < 32; ks += 16) {
            u32 ah[2][4], al[2][4], bh[4][4], bl[4][4];
            #pragma unroll
            for (int mt = 0; mt < 2; mt++) {
                ldmx4(ah[mt][0], ah[mt][1], ah[mt][2], ah[mt][3],
                      &Ah[wr + mt*16 + a_r][ks + a_k]);
                ldmx4(al[mt][0], al[mt][1], al[mt][2], al[mt][3],
                      &Al[wr + mt*16 + a_r][ks + a_k]);
            }
            #pragma unroll
            for (int p = 0; p < 4; p++) {
                ldmx4(bh[p][0], bh[p][1], bh[p][2], bh[p][3],
                      &Bh[wc + p*16 + b_r][ks + b_k]);
                ldmx4(bl[p][0], bl[p][1], bl[p][2], bl[p][3],
                      &Bl[wc + p*16 + b_r][ks + b_k]);
            }
            #pragma unroll
            for (int mt = 0; mt < 2; mt++)
                #pragma unroll
                for (int nt = 0; nt < 8; nt++) {
                    const u32* bhp = &bh[nt >> 1][(nt & 1) * 2];
                    const u32* blp = &bl[nt >> 1][(nt & 1) * 2];
                    mma16816(acc[mt][nt], ah[mt], bhp);
                    mma16816(acc[mt][nt], ah[mt], blp);
                    mma16816(acc[mt][nt], al[mt], bhp);
                }
        }
    }

    const int crow = rowBase + wr + (lane >> 2);
    const int ccol = colBase + wc + (lane & 3) * 2;
    #pragma unroll
    for (int mt = 0; mt < 2; mt++)
        #pragma unroll
        for (int nt = 0; nt < 8; nt++) {
            const int row = crow + mt * 16;
            const int col = ccol + nt * 8;
            const float b0 = bias[col], b1 = bias[col + 1];
            Y[row * 1024 + col]           = acc[mt][nt][0] + b0;
            Y[row * 1024 + col + 1]       = acc[mt][nt][1] + b1;
            Y[(row + 8) * 1024 + col]     = acc[mt][nt][2] + b0;
            Y[(row + 8) * 1024 + col + 1] = acc[mt][nt][3] + b1;
        }
}

// ---------------------------------------------------------------------------
// Tensor-core flash attention, bf16 hi/lo split (QK^T and PV), poly exp.
// 256 threads = 8 warps; warp w owns 16 q-rows. Q-tile 128, K-tile 128.
// smem: Kh/Kl [128][72] bf16 (also Q staging), Vh/Vl [128][72] bf16,
//       mb[128] float mask bias.
// ---------------------------------------------------------------------------
#define KST 72   // padded row stride (bf16) -> 144B, conflict-free ldmatrix

__global__ __launch_bounds__(256, 1) void flash_attn_tc(
    const float* __restrict__ Q, const float* __restrict__ K,
    const float* __restrict__ V, const int* __restrict__ mask,
    float* __restrict__ Out)
{
    extern __shared__ char smraw[];
    __nv_bfloat16* Kh = (__nv_bfloat16*)smraw;
    __nv_bfloat16* Kl = Kh + 128 * KST;
    __nv_bfloat16* Vh = Kl + 128 * KST;
    __nv_bfloat16* Vl = Vh + 128 * KST;
    float* mb = (float*)(Vl + 128 * KST);

    const int tid  = threadIdx.x;
    const int lane = tid & 31;
    const int warp = tid >> 5;
    const int wr   = warp * 16;       // q-row base of this warp
    const int q0 = blockIdx.x * 128;
    const int h  = blockIdx.y;
    const int b  = blockIdx.z;

    // ldmatrix lane addressing
    const int a_r = (lane & 15);
    const int a_k = (lane >> 4) * 8;
    const int b_r = ((lane >> 4) << 3) + (lane & 7);
    const int b_k = ((lane >> 3) & 1) * 8;
    const int v_r = (((lane >> 3) & 1) << 3) + (lane & 7);
    const int v_c = (lane >> 4) * 8;

    const int lrow = tid >> 1;        // 0..127
    const int ld0  = (tid & 1) * 32;  // 0 or 32

    // ---- Stage Q (scaled) into Kh/Kl, load A-fragments ----
    {
        const float* qp = Q + (b * TT + q0 + lrow) * DD + h * DK + ld0;
        #pragma unroll
        for (int u = 0; u < 8; u += 2) {  // 8 floats per iter? no: 2 float4 per iter
            float4 v0 = *(const float4*)(qp + u * 4);
            float4 v1 = *(const float4*)(qp + u * 4 + 4);
            const float f[8] = {v0.x*0.125f, v0.y*0.125f, v0.z*0.125f, v0.w*0.125f,
                                v1.x*0.125f, v1.y*0.125f, v1.z*0.125f, v1.w*0.125f};
            #pragma unroll
            for (int e = 0; e < 8; e += 2) {
                u32 hi = packbf(f[e], f[e+1]);
                float r0 = f[e]   - __int_as_float(hi << 16);
                float r1 = f[e+1] - __int_as_float(hi & 0xFFFF0000u);
                u32 lo = packbf(r0, r1);
                *(u32*)&Kh[lrow * KST + ld0 + u*4 + e] = hi;
                *(u32*)&Kl[lrow * KST + ld0 + u*4 + e] = lo;
            }
        }
    }
    __syncthreads();

    u32 qah[4][4], qal[4][4];
    #pragma unroll
    for (int ks = 0; ks < 4; ks++) {
        ldmx4(qah[ks][0], qah[ks][1], qah[ks][2], qah[ks][3],
              &Kh[(wr + a_r) * KST + ks * 16 + a_k]);
        ldmx4(qal[ks][0], qal[ks][1], qal[ks][2], qal[ks][3],
              &Kl[(wr + a_r) * KST + ks * 16 + a_k]);
    }

    float m0 = -1e30f, m1 = -1e30f, l0 = 0.f, l1 = 0.f;
    float o[8][4];
    #pragma unroll
    for (int nt = 0; nt < 8; nt++)
        #pragma unroll
        for (int q = 0; q < 4; q++) o[nt][q] = 0.f;

    for (int s0 = 0; s0 < TT; s0 += 128) {
        __syncthreads();  // prior reads (incl. Q frag loads) complete
        // ---- Load K/V tile -> bf16 hi/lo smem ----
        {
            const float* kp = K + (b * TT + s0 + lrow) * DD + h * DK + ld0;
            const float* vp = V + (b * TT + s0 + lrow) * DD + h * DK + ld0;
            #pragma unroll
            for (int u = 0; u < 8; u += 2) {
                float4 k0v = *(const float4*)(kp + u * 4);
                float4 k1v = *(const float4*)(kp + u * 4 + 4);
                float4 v0v = *(const float4*)(vp + u * 4);
                float4 v1v = *(const float4*)(vp + u * 4 + 4);
                const float fk[8] = {k0v.x, k0v.y, k0v.z, k0v.w, k1v.x, k1v.y, k1v.z, k1v.w};
                const float fv[8] = {v0v.x, v0v.y, v0v.z, v0v.w, v1v.x, v1v.y, v1v.z, v1v.w};
                #pragma unroll
                for (int e = 0; e < 8; e += 2) {
                    u32 khp = packbf(fk[e], fk[e+1]);
                    u32 klp = packbf(fk[e]   - __int_as_float(khp << 16),
                                     fk[e+1] - __int_as_float(khp & 0xFFFF0000u));
                    *(u32*)&Kh[lrow * KST + ld0 + u*4 + e] = khp;
                    *(u32*)&Kl[lrow * KST + ld0 + u*4 + e] = klp;
                    u32 vhp = packbf(fv[e], fv[e+1]);
                    u32 vlp = packbf(fv[e]   - __int_as_float(vhp << 16),
                                     fv[e+1] - __int_as_float(vhp & 0xFFFF0000u));
                    *(u32*)&Vh[lrow * KST + ld0 + u*4 + e] = vhp;
                    *(u32*)&Vl[lrow * KST + ld0 + u*4 + e] = vlp;
                }
            }
            if (tid < 128)
                mb[tid] = (mask[b * TT + s0 + tid] != 0) ? 0.f : -1e30f;
        }
        __syncthreads();

        // ---- Scores S = Qs @ K^T (hi/lo 3-MMA) ----
        float s[16][4];
        #pragma unroll
        for (int nt = 0; nt < 16; nt++)
            #pragma unroll
            for (int q = 0; q < 4; q++) s[nt][q] = 0.f;

        #pragma unroll
        for (int np = 0; np < 8; np++) {
            #pragma unroll
            for (int ks = 0; ks < 4; ks++) {
                u32 bh[4], bl[4];
                ldmx4(bh[0], bh[1], bh[2], bh[3],
                      &Kh[(np*16 + b_r) * KST + ks*16 + b_k]);
                ldmx4(bl[0], bl[1], bl[2], bl[3],
                      &Kl[(np*16 + b_r) * KST + ks*16 + b_k]);
                mma16816(s[2*np],   qah[ks], &bh[0]);
                mma16816(s[2*np],   qal[ks], &bh[0]);
                mma16816(s[2*np],   qah[ks], &bl[0]);
                mma16816(s[2*np+1], qah[ks], &bh[2]);
                mma16816(s[2*np+1], qal[ks], &bh[2]);
                mma16816(s[2*np+1], qah[ks], &bl[2]);
            }
        }

        // ---- Mask bias + online softmax ----
        float mx0 = m0, mx1 = m1;
        #pragma unroll
        for (int nt = 0; nt < 16; nt++) {
            float2 mbv = *(const float2*)&mb[nt*8 + (lane & 3)*2];
            s[nt][0] += mbv.x; s[nt][1] += mbv.y;
            s[nt][2] += mbv.x; s[nt][3] += mbv.y;
            mx0 = fmaxf(mx0, fmaxf(s[nt][0], s[nt][1]));
            mx1 = fmaxf(mx1, fmaxf(s[nt][2], s[nt][3]));
        }
        mx0 = fmaxf(mx0, __shfl_xor_sync(0xffffffffu, mx0, 1));
        mx0 = fmaxf(mx0, __shfl_xor_sync(0xffffffffu, mx0, 2));
        mx1 = fmaxf(mx1, __shfl_xor_sync(0xffffffffu, mx1, 1));
        mx1 = fmaxf(mx1, __shfl_xor_sync(0xffffffffu, mx1, 2));
        const float sc0 = fast_exp(m0 - mx0);
        const float sc1 = fast_exp(m1 - mx1);
        m0 = mx0; m1 = mx1;
        float rs0 = 0.f, rs1 = 0.f;
        #pragma unroll
        for (int nt = 0; nt < 16; nt++) {
            s[nt][0] = fast_exp(s[nt][0] - mx0);
            s[nt][1] = fast_exp(s[nt][1] - mx0);
            s[nt][2] = fast_exp(s[nt][2] - mx1);
            s[nt][3] = fast_exp(s[nt][3] - mx1);
            rs0 += s[nt][0] + s[nt][1];
            rs1 += s[nt][2] + s[nt][3];
        }
        rs0 += __shfl_xor_sync(0xffffffffu, rs0, 1);
        rs0 += __shfl_xor_sync(0xffffffffu, rs0, 2);
        rs1 += __shfl_xor_sync(0xffffffffu, rs1, 1);
        rs1 += __shfl_xor_sync(0xffffffffu, rs1, 2);
        l0 = l0 * sc0 + rs0;
        l1 = l1 * sc1 + rs1;
        #pragma unroll
        for (int nt = 0; nt < 8; nt++) {
            o[nt][0] *= sc0; o[nt][1] *= sc0;
            o[nt][2] *= sc1; o[nt][3] *= sc1;
        }

        // ---- O += P @ V (P from accumulators, hi/lo 3-MMA) ----
        #pragma unroll
        for (int kc = 0; kc < 8; kc++) {
            u32 pah[4], pal[4];
            #pragma unroll
            for (int half = 0; half < 2; half++) {
                const float* sp = s[2*kc + half];
                u32 h0 = packbf(sp[0], sp[1]);
                u32 h1 = packbf(sp[2], sp[3]);
                pah[half*2 + 0] = h0;  // wrong slot for half=1? see mapping below
                pah[half*2 + 1] = h1;
                pal[half*2 + 0] = packbf(sp[0] - __int_as_float(h0 << 16),
                                         sp[1] - __int_as_float(h0 & 0xFFFF0000u));
                pal[half*2 + 1] = packbf(sp[2] - __int_as_float(h1 << 16),
                                         sp[3] - __int_as_float(h1 & 0xFFFF0000u));
            }
            // mapping: a0=(r,k0..1)=nt even c0,c1 ; a1=(r+8,k0..1)=nt even c2,c3
            //          a2=(r,k8..9)=nt odd c0,c1 ; a3=(r+8,k8..9)=nt odd c2,c3
            // pah as filled: [0]=even c0c1, [1]=even c2c3, [2]=odd c0c1, [3]=odd c2c3  ✓
            #pragma unroll
            for (int nb = 0; nb < 4; nb++) {
                u32 vh[4], vl[4];
                ldmx4t(vh[0], vh[1], vh[2], vh[3],
                       &Vh[(kc*16 + v_r) * KST + nb*16 + v_c]);
                ldmx4t(vl[0], vl[1], vl[2], vl[3],
                       &Vl[(kc*16 + v_r) * KST + nb*16 + v_c]);
                mma16816(o[2*nb],   pah, &vh[0]);
                mma16816(o[2*nb],   pal, &vh[0]);
                mma16816(o[2*nb],   pah, &vl[0]);
                mma16816(o[2*nb+1], pah, &vh[2]);
                mma16816(o[2*nb+1], pal, &vh[2]);
                mma16816(o[2*nb+1], pah, &vl[2]);
            }
        }
    }

    // ---- Epilogue ----
    const float inv0 = 1.f / l0;
    const float inv1 = 1.f / l1;
    const int row0 = b * TT + q0 + wr + (lane >> 2);
    #pragma unroll
    for (int nt = 0; nt < 8; nt++) {
        const int dcol = h * DK + (nt >> 1) * 16 + (nt & 1) * 8 + (lane & 3) * 2;
        *(float2*)&Out[row0 * DD + dcol] =
            make_float2(o[nt][0] * inv0, o[nt][1] * inv0);
        *(float2*)&Out[(row0 + 8) * DD + dcol] =
            make_float2(o[nt][2] * inv1, o[nt][3] * inv1);
    }
}

// ---------------------------------------------------------------------------
extern "C" void kernel_launch(void* const* d_in, const int* in_sizes, int n_in,
                              void* d_out, int out_size)
{
    const float* query = (const float*)d_in[0];
    const float* key   = (const float*)d_in[1];
    const float* value = (const float*)d_in[2];
    const int*   mask  = (const int*)d_in[3];
    const float* Wq = (const float*)d_in[4];
    const float* bq = (const float*)d_in[5];
    const float* Wk = (const float*)d_in[6];
    const float* bk = (const float*)d_in[7];
    const float* Wv = (const float*)d_in[8];
    const float* bv = (const float*)d_in[9];
    const float* Wo = (const float*)d_in[10];
    const float* bo = (const float*)d_in[11];
    float* out = (float*)d_out;

    float *gQ, *gK, *gV, *gC;
    cudaGetSymbolAddress((void**)&gQ, g_Q);
    cudaGetSymbolAddress((void**)&gK, g_K);
    cudaGetSymbolAddress((void**)&gV, g_V);
    cudaGetSymbolAddress((void**)&gC, g_C);

    dim3 ggrid(1024 / 128, 4096 / 128);  // (8, 32)
    gemm_bias_tc<<<ggrid, 256>>>(query, Wq, bq, gQ);
    gemm_bias_tc<<<ggrid, 256>>>(key,   Wk, bk, gK);
    gemm_bias_tc<<<ggrid, 256>>>(value, Wv, bv, gV);

    const int fsmem = 4 * 128 * KST * 2 + 128 * 4;  // 74240 B
    cudaFuncSetAttribute(flash_attn_tc,
                         cudaFuncAttributeMaxDynamicSharedMemorySize, fsmem);
    dim3 fgrid(TT / 128, HH, BB);  // (16, 16, 2)
    flash_attn_tc<<<fgrid, 256, fsmem>>>(gQ, gK, gV, mask, gC);

    gemm_bias_tc<<<ggrid, 256>>>(gC, Wo, bo, out);
}

// round 7
// speedup vs baseline: 2.1351x; 1.1705x over previous
#include <cuda_runtime.h>
#include <cuda_bf16.h>
#include <math.h>

#define BB 2
#define TT 2048
#define DD 1024
#define HH 16
#define DK 64

typedef unsigned long long u64;
typedef unsigned int u32;

__device__ __forceinline__ void ldmx4(u32& r0, u32& r1, u32& r2, u32& r3, const void* p) {
    u32 addr = (u32)__cvta_generic_to_shared(p);
    asm volatile("ldmatrix.sync.aligned.m8n8.x4.shared.b16 {%0,%1,%2,%3},[%4];"
                 : "=r"(r0), "=r"(r1), "=r"(r2), "=r"(r3) : "r"(addr));
}
__device__ __forceinline__ void ldmx4t(u32& r0, u32& r1, u32& r2, u32& r3, const void* p) {
    u32 addr = (u32)__cvta_generic_to_shared(p);
    asm volatile("ldmatrix.sync.aligned.m8n8.x4.trans.shared.b16 {%0,%1,%2,%3},[%4];"
                 : "=r"(r0), "=r"(r1), "=r"(r2), "=r"(r3) : "r"(addr));
}
__device__ __forceinline__ void mma16816(float* c, const u32* a, const u32* b) {
    asm volatile(
        "mma.sync.aligned.m16n8k16.row.col.f32.bf16.bf16.f32 "
        "{%0,%1,%2,%3},{%4,%5,%6,%7},{%8,%9},{%0,%1,%2,%3};"
        : "+f"(c[0]), "+f"(c[1]), "+f"(c[2]), "+f"(c[3])
        : "r"(a[0]), "r"(a[1]), "r"(a[2]), "r"(a[3]), "r"(b[0]), "r"(b[1]));
}
__device__ __forceinline__ u32 packbf(float lo, float hi) {
    u32 r; asm("cvt.rn.satfinite.bf16x2.f32 %0,%1,%2;" : "=r"(r) : "f"(hi), "f"(lo));
    return r;
}
__device__ __forceinline__ void cp16(u32 dst, const void* src) {
    asm volatile("cp.async.cg.shared.global [%0],[%1],16;" :: "r"(dst), "l"(src));
}
#define CP_COMMIT() asm volatile("cp.async.commit_group;")
#define CP_WAIT1()  asm volatile("cp.async.wait_group 1;")
#define CP_WAIT0()  asm volatile("cp.async.wait_group 0;")

// MUFU-free exp: 2^(x*log2e), magic-number rounding, deg-5 poly. x <= ~0.
__device__ __forceinline__ float fast_exp(float x) {
    float z = fmaxf(x * 1.4426950408889634f, -126.0f);
    float zi = z + 12582912.0f;
    float f = z - (zi - 12582912.0f);
    int n = __float_as_int(zi) - 0x4B400000;
    float p = 1.3333558e-3f;
    p = fmaf(p, f, 9.6181291e-3f);
    p = fmaf(p, f, 5.5504109e-2f);
    p = fmaf(p, f, 2.4022651e-1f);
    p = fmaf(p, f, 6.9314718e-1f);
    p = fmaf(p, f, 1.0f);
    return p * __int_as_float((n + 127) << 23);
}

// ---------------- scratch (bf16 hi/lo everywhere) ----------------
__device__ __nv_bfloat16 g_Xh[BB*TT*DD], g_Xl[BB*TT*DD];
__device__ __nv_bfloat16 g_Wqh[DD*DD], g_Wql[DD*DD];
__device__ __nv_bfloat16 g_Wkh[DD*DD], g_Wkl[DD*DD];
__device__ __nv_bfloat16 g_Wvh[DD*DD], g_Wvl[DD*DD];
__device__ __nv_bfloat16 g_Woh[DD*DD], g_Wol[DD*DD];
__device__ __nv_bfloat16 g_Qh[BB*TT*DD], g_Ql[BB*TT*DD];
__device__ __nv_bfloat16 g_Kh[BB*TT*DD], g_Kl[BB*TT*DD];
__device__ __nv_bfloat16 g_Vh[BB*TT*DD], g_Vl[BB*TT*DD];
__device__ __nv_bfloat16 g_Ch[BB*TT*DD], g_Cl[BB*TT*DD];

// ---------------------------------------------------------------------------
// fp32 -> bf16 hi/lo split (memory-bound)
// ---------------------------------------------------------------------------
__global__ __launch_bounds__(256) void convert_hl(
    const float4* __restrict__ X, u32* __restrict__ H, u32* __restrict__ L, int n4)
{
    int i = blockIdx.x * blockDim.x + threadIdx.x;
    if (i >= n4) return;
    float4 v = X[i];
    u32 h0 = packbf(v.x, v.y), h1 = packbf(v.z, v.w);
    u32 l0 = packbf(v.x - __int_as_float(h0 << 16), v.y - __int_as_float(h0 & 0xFFFF0000u));
    u32 l1 = packbf(v.z - __int_as_float(h1 << 16), v.w - __int_as_float(h1 & 0xFFFF0000u));
    *(uint2*)&H[i * 2] = make_uint2(h0, h1);
    *(uint2*)&L[i * 2] = make_uint2(l0, l1);
}

// ---------------------------------------------------------------------------
// GEMM on pre-split bf16: Y = X @ W^T + bias. CTA 128x128, BK=32, cp.async x2.
// MODE 0: write fp32 to Yf.  MODE 1: write bf16 hi/lo (scaled) to Yh/Yl.
// smem stage: Ah/Al/Bh/Bl [128][40] bf16 -> 40960B; 2 stages = 81920B.
// ---------------------------------------------------------------------------
#define GW 40
#define GSTAGE (4 * 128 * GW)            // bf16 per stage

template<int MODE>
__global__ __launch_bounds__(256, 1) void gemm_tc_hl(
    const __nv_bfloat16* __restrict__ Xh, const __nv_bfloat16* __restrict__ Xl,
    const __nv_bfloat16* __restrict__ Wh, const __nv_bfloat16* __restrict__ Wl,
    const float* __restrict__ bias, float* __restrict__ Yf,
    __nv_bfloat16* __restrict__ Yh, __nv_bfloat16* __restrict__ Yl, float oscale)
{
    extern __shared__ char smraw[];
    __nv_bfloat16* SM = (__nv_bfloat16*)smraw;
    const u32 smb = (u32)__cvta_generic_to_shared(smraw);

    const int tid  = threadIdx.x;
    const int lane = tid & 31;
    const int warp = tid >> 5;
    const int wr = (warp & 3) * 32;
    const int wc = (warp >> 2) * 64;
    const int rowBase = blockIdx.y * 128;
    const int colBase = blockIdx.x * 128;

    // cp.async mapping: 64 threads per array; each thread 2 rows x 4 chunks(16B)
    const int la = tid >> 6;             // 0:Xh 1:Xl 2:Wh 3:Wl
    const int r0 = (tid & 63) * 2;
    const __nv_bfloat16* sp = (la == 0) ? Xh : (la == 1) ? Xl : (la == 2) ? Wh : Wl;
    const __nv_bfloat16* sbase = sp + (u64)(((la < 2) ? rowBase : colBase) + r0) * 1024;
    const u32 dbase = smb + (u32)(la * 128 * GW + r0 * GW) * 2;

    const int a_r = (lane & 15);
    const int a_k = (lane >> 4) * 8;
    const int b_r = ((lane >> 4) << 3) + (lane & 7);
    const int b_k = ((lane >> 3) & 1) * 8;

    float acc[2][8][4];
    #pragma unroll
    for (int mt = 0; mt < 2; mt++)
        #pragma unroll
        for (int nt = 0; nt < 8; nt++)
            #pragma unroll
            for (int q = 0; q < 4; q++) acc[mt][nt][q] = 0.f;

    // prologue: stages 0,1
    #pragma unroll
    for (int st = 0; st < 2; st++) {
        #pragma unroll
        for (int rr = 0; rr < 2; rr++)
            #pragma unroll
            for (int c = 0; c < 4; c++)
                cp16(dbase + (u32)(st * GSTAGE + rr * GW + c * 8) * 2,
                     sbase + rr * 1024 + st * 32 + c * 8);
        CP_COMMIT();
    }

    for (int kt = 0; kt < 32; kt++) {
        if (kt < 31) CP_WAIT1(); else CP_WAIT0();
        __syncthreads();

        const int buf = kt & 1;
        const __nv_bfloat16* Ah = SM + buf * GSTAGE;
        const __nv_bfloat16* Al = Ah + 128 * GW;
        const __nv_bfloat16* Bh = Al + 128 * GW;
        const __nv_bfloat16* Bl = Bh + 128 * GW;

        #pragma unroll
        for (int ks = 0; ks < 32; ks += 16) {
            u32 ah[2][4], al[2][4], bh[4][4], bl[4][4];
            #pragma unroll
            for (int mt = 0; mt < 2; mt++) {
                ldmx4(ah[mt][0], ah[mt][1], ah[mt][2], ah[mt][3],
                      &Ah[(wr + mt*16 + a_r) * GW + ks + a_k]);
                ldmx4(al[mt][0], al[mt][1], al[mt][2], al[mt][3],
                      &Al[(wr + mt*16 + a_r) * GW + ks + a_k]);
            }
            #pragma unroll
            for (int p = 0; p < 4; p++) {
                ldmx4(bh[p][0], bh[p][1], bh[p][2], bh[p][3],
                      &Bh[(wc + p*16 + b_r) * GW + ks + b_k]);
                ldmx4(bl[p][0], bl[p][1], bl[p][2], bl[p][3],
                      &Bl[(wc + p*16 + b_r) * GW + ks + b_k]);
            }
            #pragma unroll
            for (int mt = 0; mt < 2; mt++)
                #pragma unroll
                for (int nt = 0; nt < 8; nt++) {
                    const u32* bhp = &bh[nt >> 1][(nt & 1) * 2];
                    const u32* blp = &bl[nt >> 1][(nt & 1) * 2];
                    mma16816(acc[mt][nt], ah[mt], bhp);
                    mma16816(acc[mt][nt], ah[mt], blp);
                    mma16816(acc[mt][nt], al[mt], bhp);
                }
        }
        __syncthreads();
        if (kt + 2 < 32) {
            #pragma unroll
            for (int rr = 0; rr < 2; rr++)
                #pragma unroll
                for (int c = 0; c < 4; c++)
                    cp16(dbase + (u32)(buf * GSTAGE + rr * GW + c * 8) * 2,
                         sbase + rr * 1024 + (kt + 2) * 32 + c * 8);
            CP_COMMIT();
        }
    }

    const int crow = rowBase + wr + (lane >> 2);
    const int ccol = colBase + wc + (lane & 3) * 2;
    #pragma unroll
    for (int mt = 0; mt < 2; mt++)
        #pragma unroll
        for (int nt = 0; nt < 8; nt++) {
            const int row = crow + mt * 16;
            const int col = ccol + nt * 8;
            const float b0 = bias[col], b1 = bias[col + 1];
            float y00 = acc[mt][nt][0] + b0, y01 = acc[mt][nt][1] + b1;
            float y10 = acc[mt][nt][2] + b0, y11 = acc[mt][nt][3] + b1;
            if (MODE == 0) {
                Yf[(u64)row * 1024 + col]           = y00;
                Yf[(u64)row * 1024 + col + 1]       = y01;
                Yf[(u64)(row + 8) * 1024 + col]     = y10;
                Yf[(u64)(row + 8) * 1024 + col + 1] = y11;
            } else {
                y00 *= oscale; y01 *= oscale; y10 *= oscale; y11 *= oscale;
                u32 h0 = packbf(y00, y01);
                u32 l0 = packbf(y00 - __int_as_float(h0 << 16),
                                y01 - __int_as_float(h0 & 0xFFFF0000u));
                u32 h1 = packbf(y10, y11);
                u32 l1 = packbf(y10 - __int_as_float(h1 << 16),
                                y11 - __int_as_float(h1 & 0xFFFF0000u));
                *(u32*)&Yh[(u64)row * 1024 + col]       = h0;
                *(u32*)&Yl[(u64)row * 1024 + col]       = l0;
                *(u32*)&Yh[(u64)(row + 8) * 1024 + col] = h1;
                *(u32*)&Yl[(u64)(row + 8) * 1024 + col] = l1;
            }
        }
}

// ---------------------------------------------------------------------------
// Tensor-core flash attention on pre-split bf16, cp.async double-buffered K/V.
// 256 thr = 8 warps, warp owns 16 q-rows. Q-tile 128, key-tile 128.
// smem: Qh/Ql [128][72] + 2 KV stages (Kh/Kl/Vh/Vl [128][72]) + mb[2][128]f.
// ---------------------------------------------------------------------------
#define KST 72
#define FARR (128 * KST)                 // bf16 per array
#define FSTAGE (4 * FARR)                // bf16 per KV stage

__global__ __launch_bounds__(256, 1) void flash_attn_tc(
    const __nv_bfloat16* __restrict__ Qhg, const __nv_bfloat16* __restrict__ Qlg,
    const __nv_bfloat16* __restrict__ Khg, const __nv_bfloat16* __restrict__ Klg,
    const __nv_bfloat16* __restrict__ Vhg, const __nv_bfloat16* __restrict__ Vlg,
    const int* __restrict__ mask,
    __nv_bfloat16* __restrict__ Ch, __nv_bfloat16* __restrict__ Cl)
{
    extern __shared__ char smraw[];
    __nv_bfloat16* Qh_s = (__nv_bfloat16*)smraw;
    __nv_bfloat16* Ql_s = Qh_s + FARR;
    __nv_bfloat16* KV   = Ql_s + FARR;
    float* mb = (float*)(KV + 2 * FSTAGE);
    const u32 kvb = (u32)__cvta_generic_to_shared(KV);

    const int tid  = threadIdx.x;
    const int lane = tid & 31;
    const int warp = tid >> 5;
    const int wr   = warp * 16;
    const int q0 = blockIdx.x * 128;
    const int h  = blockIdx.y;
    const int b  = blockIdx.z;

    const int a_r = (lane & 15);
    const int a_k = (lane >> 4) * 8;
    const int b_r = ((lane >> 4) << 3) + (lane & 7);
    const int b_k = ((lane >> 3) & 1) * 8;
    const int v_r = (((lane >> 3) & 1) << 3) + (lane & 7);
    const int v_c = (lane >> 4) * 8;

    // ---- Q staging (plain copies) ----
    {
        const int row = tid >> 1;
        const int half = (tid & 1) * 32;
        const u64 gro = (u64)(b * TT + q0 + row) * DD + h * DK + half;
        #pragma unroll
        for (int c = 0; c < 4; c++) {
            *(uint4*)&Qh_s[row * KST + half + c * 8] = *(const uint4*)&Qhg[gro + c * 8];
            *(uint4*)&Ql_s[row * KST + half + c * 8] = *(const uint4*)&Qlg[gro + c * 8];
        }
    }
    __syncthreads();
    u32 qah[4][4], qal[4][4];
    #pragma unroll
    for (int ks = 0; ks < 4; ks++) {
        ldmx4(qah[ks][0], qah[ks][1], qah[ks][2], qah[ks][3],
              &Qh_s[(wr + a_r) * KST + ks * 16 + a_k]);
        ldmx4(qal[ks][0], qal[ks][1], qal[ks][2], qal[ks][3],
              &Ql_s[(wr + a_r) * KST + ks * 16 + a_k]);
    }

    // cp.async mapping for KV: 64 threads per array, 2 rows x 8 chunks each
    const int la = tid >> 6;             // 0:Kh 1:Kl 2:Vh 3:Vl
    const int r0 = (tid & 63) * 2;
    const __nv_bfloat16* sp = (la == 0) ? Khg : (la == 1) ? Klg : (la == 2) ? Vhg : Vlg;
    const u32 dbase = kvb + (u32)(la * FARR + r0 * KST) * 2;

    // issue KV stage t into buf
    auto issueKV = [&](int t, int buf) {
        const int s0 = t * 128;
        const __nv_bfloat16* sbase = sp + (u64)(b * TT + s0 + r0) * DD + h * DK;
        #pragma unroll
        for (int rr = 0; rr < 2; rr++)
            #pragma unroll
            for (int c = 0; c < 8; c++)
                cp16(dbase + (u32)(buf * FSTAGE + rr * KST + c * 8) * 2,
                     sbase + (u64)rr * DD + c * 8);
        if (tid < 128)
            mb[buf * 128 + tid] = (mask[b * TT + s0 + tid] != 0) ? 0.f : -1e30f;
        CP_COMMIT();
    };

    issueKV(0, 0);
    issueKV(1, 1);

    float m0 = -1e30f, m1 = -1e30f, l0 = 0.f, l1 = 0.f;
    float o[8][4];
    #pragma unroll
    for (int nt = 0; nt < 8; nt++)
        #pragma unroll
        for (int q = 0; q < 4; q++) o[nt][q] = 0.f;

    for (int t = 0; t < 16; t++) {
        if (t < 15) CP_WAIT1(); else CP_WAIT0();
        __syncthreads();
        const int buf = t & 1;
        const __nv_bfloat16* Khs = KV + buf * FSTAGE;
        const __nv_bfloat16* Kls = Khs + FARR;
        const __nv_bfloat16* Vhs = Kls + FARR;
        const __nv_bfloat16* Vls = Vhs + FARR;
        const float* mbp = mb + buf * 128;

        // ---- S = Qs @ K^T ----
        float s[16][4];
        #pragma unroll
        for (int nt = 0; nt < 16; nt++)
            #pragma unroll
            for (int q = 0; q < 4; q++) s[nt][q] = 0.f;

        #pragma unroll
        for (int np = 0; np < 8; np++) {
            #pragma unroll
            for (int ks = 0; ks < 4; ks++) {
                u32 bh[4], bl[4];
                ldmx4(bh[0], bh[1], bh[2], bh[3],
                      &Khs[(np*16 + b_r) * KST + ks*16 + b_k]);
                ldmx4(bl[0], bl[1], bl[2], bl[3],
                      &Kls[(np*16 + b_r) * KST + ks*16 + b_k]);
                mma16816(s[2*np],   qah[ks], &bh[0]);
                mma16816(s[2*np],   qal[ks], &bh[0]);
                mma16816(s[2*np],   qah[ks], &bl[0]);
                mma16816(s[2*np+1], qah[ks], &bh[2]);
                mma16816(s[2*np+1], qal[ks], &bh[2]);
                mma16816(s[2*np+1], qah[ks], &bl[2]);
            }
        }

        // ---- mask bias + online softmax ----
        float mx0 = m0, mx1 = m1;
        #pragma unroll
        for (int nt = 0; nt < 16; nt++) {
            float2 mbv = *(const float2*)&mbp[nt*8 + (lane & 3)*2];
            s[nt][0] += mbv.x; s[nt][1] += mbv.y;
            s[nt][2] += mbv.x; s[nt][3] += mbv.y;
            mx0 = fmaxf(mx0, fmaxf(s[nt][0], s[nt][1]));
            mx1 = fmaxf(mx1, fmaxf(s[nt][2], s[nt][3]));
        }
        mx0 = fmaxf(mx0, __shfl_xor_sync(0xffffffffu, mx0, 1));
        mx0 = fmaxf(mx0, __shfl_xor_sync(0xffffffffu, mx0, 2));
        mx1 = fmaxf(mx1, __shfl_xor_sync(0xffffffffu, mx1, 1));
        mx1 = fmaxf(mx1, __shfl_xor_sync(0xffffffffu, mx1, 2));
        const float sc0 = fast_exp(m0 - mx0);
        const float sc1 = fast_exp(m1 - mx1);
        m0 = mx0; m1 = mx1;
        float rs0 = 0.f, rs1 = 0.f;
        #pragma unroll
        for (int nt = 0; nt < 16; nt++) {
            s[nt][0] = fast_exp(s[nt][0] - mx0);
            s[nt][1] = fast_exp(s[nt][1] - mx0);
            s[nt][2] = fast_exp(s[nt][2] - mx1);
            s[nt][3] = fast_exp(s[nt][3] - mx1);
            rs0 += s[nt][0] + s[nt][1];
            rs1 += s[nt][2] + s[nt][3];
        }
        rs0 += __shfl_xor_sync(0xffffffffu, rs0, 1);
        rs0 += __shfl_xor_sync(0xffffffffu, rs0, 2);
        rs1 += __shfl_xor_sync(0xffffffffu, rs1, 1);
        rs1 += __shfl_xor_sync(0xffffffffu, rs1, 2);
        l0 = l0 * sc0 + rs0;
        l1 = l1 * sc1 + rs1;
        #pragma unroll
        for (int nt = 0; nt < 8; nt++) {
            o[nt][0] *= sc0; o[nt][1] *= sc0;
            o[nt][2] *= sc1; o[nt][3] *= sc1;
        }

        // ---- O += P @ V ----
        #pragma unroll
        for (int kc = 0; kc < 8; kc++) {
            u32 pah[4], pal[4];
            #pragma unroll
            for (int half = 0; half < 2; half++) {
                const float* spv = s[2*kc + half];
                u32 h0 = packbf(spv[0], spv[1]);
                u32 h1 = packbf(spv[2], spv[3]);
                pah[half*2 + 0] = h0;
                pah[half*2 + 1] = h1;
                pal[half*2 + 0] = packbf(spv[0] - __int_as_float(h0 << 16),
                                         spv[1] - __int_as_float(h0 & 0xFFFF0000u));
                pal[half*2 + 1] = packbf(spv[2] - __int_as_float(h1 << 16),
                                         spv[3] - __int_as_float(h1 & 0xFFFF0000u));
            }
            #pragma unroll
            for (int nb = 0; nb < 4; nb++) {
                u32 vh[4], vl[4];
                ldmx4t(vh[0], vh[1], vh[2], vh[3],
                       &Vhs[(kc*16 + v_r) * KST + nb*16 + v_c]);
                ldmx4t(vl[0], vl[1], vl[2], vl[3],
                       &Vls[(kc*16 + v_r) * KST + nb*16 + v_c]);
                mma16816(o[2*nb],   pah, &vh[0]);
                mma16816(o[2*nb],   pal, &vh[0]);
                mma16816(o[2*nb],   pah, &vl[0]);
                mma16816(o[2*nb+1], pah, &vh[2]);
                mma16816(o[2*nb+1], pal, &vh[2]);
                mma16816(o[2*nb+1], pah, &vl[2]);
            }
        }

        __syncthreads();
        if (t + 2 < 16) issueKV(t + 2, buf);
    }

    // ---- epilogue: write C as bf16 hi/lo ----
    const float inv0 = 1.f / l0;
    const float inv1 = 1.f / l1;
    const int row0 = b * TT + q0 + wr + (lane >> 2);
    #pragma unroll
    for (int nt = 0; nt < 8; nt++) {
        const int dcol = h * DK + (nt >> 1) * 16 + (nt & 1) * 8 + (lane & 3) * 2;
        float y00 = o[nt][0] * inv0, y01 = o[nt][1] * inv0;
        float y10 = o[nt][2] * inv1, y11 = o[nt][3] * inv1;
        u32 h0 = packbf(y00, y01);
        u32 l0p = packbf(y00 - __int_as_float(h0 << 16),
                         y01 - __int_as_float(h0 & 0xFFFF0000u));
        u32 h1 = packbf(y10, y11);
        u32 l1p = packbf(y10 - __int_as_float(h1 << 16),
                         y11 - __int_as_float(h1 & 0xFFFF0000u));
        *(u32*)&Ch[(u64)row0 * DD + dcol]       = h0;
        *(u32*)&Cl[(u64)row0 * DD + dcol]       = l0p;
        *(u32*)&Ch[(u64)(row0 + 8) * DD + dcol] = h1;
        *(u32*)&Cl[(u64)(row0 + 8) * DD + dcol] = l1p;
    }
}

// ---------------------------------------------------------------------------
extern "C" void kernel_launch(void* const* d_in, const int* in_sizes, int n_in,
                              void* d_out, int out_size)
{
    const float* query = (const float*)d_in[0];
    const float* key   = (const float*)d_in[1];
    const float* value = (const float*)d_in[2];
    const int*   mask  = (const int*)d_in[3];
    const float* Wq = (const float*)d_in[4];
    const float* bq = (const float*)d_in[5];
    const float* Wk = (const float*)d_in[6];
    const float* bk = (const float*)d_in[7];
    const float* Wv = (const float*)d_in[8];
    const float* bv = (const float*)d_in[9];
    const float* Wo = (const float*)d_in[10];
    const float* bo = (const float*)d_in[11];
    float* out = (float*)d_out;

    __nv_bfloat16 *Xh, *Xl, *Wqh, *Wql, *Wkh, *Wkl, *Wvh, *Wvl, *Woh, *Wol;
    __nv_bfloat16 *Qh, *Ql, *Kh, *Kl, *Vh, *Vl, *Ch, *Cl;
    cudaGetSymbolAddress((void**)&Xh, g_Xh);   cudaGetSymbolAddress((void**)&Xl, g_Xl);
    cudaGetSymbolAddress((void**)&Wqh, g_Wqh); cudaGetSymbolAddress((void**)&Wql, g_Wql);
    cudaGetSymbolAddress((void**)&Wkh, g_Wkh); cudaGetSymbolAddress((void**)&Wkl, g_Wkl);
    cudaGetSymbolAddress((void**)&Wvh, g_Wvh); cudaGetSymbolAddress((void**)&Wvl, g_Wvl);
    cudaGetSymbolAddress((void**)&Woh, g_Woh); cudaGetSymbolAddress((void**)&Wol, g_Wol);
    cudaGetSymbolAddress((void**)&Qh, g_Qh);   cudaGetSymbolAddress((void**)&Ql, g_Ql);
    cudaGetSymbolAddress((void**)&Kh, g_Kh);   cudaGetSymbolAddress((void**)&Kl, g_Kl);
    cudaGetSymbolAddress((void**)&Vh, g_Vh);   cudaGetSymbolAddress((void**)&Vl, g_Vl);
    cudaGetSymbolAddress((void**)&Ch, g_Ch);   cudaGetSymbolAddress((void**)&Cl, g_Cl);

    const int gsmem = GSTAGE * 2 * 2;            // 81920 B
    const int fsmem = (2*FARR + 2*FSTAGE) * 2 + 2*128*4;  // 185344 B
    static bool attrDone = false;
    if (!attrDone) {
        cudaFuncSetAttribute(gemm_tc_hl<0>, cudaFuncAttributeMaxDynamicSharedMemorySize, gsmem);
        cudaFuncSetAttribute(gemm_tc_hl<1>, cudaFuncAttributeMaxDynamicSharedMemorySize, gsmem);
        cudaFuncSetAttribute(flash_attn_tc, cudaFuncAttributeMaxDynamicSharedMemorySize, fsmem);
        attrDone = true;
    }

    const int nW4 = DD * DD / 4;          // 262144
    const int nX4 = BB * TT * DD / 4;     // 1048576
    convert_hl<<<nW4 / 256, 256>>>((const float4*)Wq, (u32*)Wqh, (u32*)Wql, nW4);
    convert_hl<<<nW4 / 256, 256>>>((const float4*)Wk, (u32*)Wkh, (u32*)Wkl, nW4);
    convert_hl<<<nW4 / 256, 256>>>((const float4*)Wv, (u32*)Wvh, (u32*)Wvl, nW4);
    convert_hl<<<nW4 / 256, 256>>>((const float4*)Wo, (u32*)Woh, (u32*)Wol, nW4);

    dim3 ggrid(1024 / 128, 4096 / 128);   // (8, 32)

    convert_hl<<<nX4 / 256, 256>>>((const float4*)query, (u32*)Xh, (u32*)Xl, nX4);
    gemm_tc_hl<1><<<ggrid, 256, gsmem>>>(Xh, Xl, Wqh, Wql, bq, nullptr, Qh, Ql, 0.125f);
    convert_hl<<<nX4 / 256, 256>>>((const float4*)key, (u32*)Xh, (u32*)Xl, nX4);
    gemm_tc_hl<1><<<ggrid, 256, gsmem>>>(Xh, Xl, Wkh, Wkl, bk, nullptr, Kh, Kl, 1.0f);
    convert_hl<<<nX4 / 256, 256>>>((const float4*)value, (u32*)Xh, (u32*)Xl, nX4);
    gemm_tc_hl<1><<<ggrid, 256, gsmem>>>(Xh, Xl, Wvh, Wvl, bv, nullptr, Vh, Vl, 1.0f);

    dim3 fgrid(TT / 128, HH, BB);         // (16, 16, 2)
    flash_attn_tc<<<fgrid, 256, fsmem>>>(Qh, Ql, Kh, Kl, Vh, Vl, mask, Ch, Cl);

    gemm_tc_hl<0><<<ggrid, 256, gsmem>>>(Ch, Cl, Woh, Wol, bo, out, nullptr, nullptr, 1.0f);
}